// round 15
// baseline (speedup 1.0000x reference)
#include <cuda_runtime.h>
#include <cuda_fp16.h>
#include <math.h>
#include <stdint.h>

// Problem shape
#define BATCH 32
#define LDIM  512
#define DDIM  768
#define EPSF  1e-5f

// Gram tiling: 128(m) x 64(n) tiles on the 6x12 grid, cover tj >= 2*ti -> 42 tiles.
#define NTILES  42
#define BK      64                   // k (l-rows) per stage
#define NCHUNK  (LDIM / BK)          // 8
#define STAGES  3
#define A_BYTES (BK * 128 * 2)       // 64 k-rows x 128 m-halfs = 16384 (256B rows)
#define B_BYTES (BK * 64 * 2)        // 64 k-rows x 64 n-halfs  = 8192  (128B rows)
#define STAGE_BYTES (A_BYTES + B_BYTES)          // 24576
#define SMEM_BYTES  (STAGES * STAGE_BYTES)       // 73728

// Scratch: weight-folded fp16 copy in NATURAL layout  Zh[b][l][d]  (24 MB)
__device__ __align__(16) __half g_Zh[BATCH * LDIM * DDIM];

__device__ __forceinline__ void cp16(uint32_t saddr, const void* g) {
    asm volatile("cp.async.cg.shared.global [%0], [%1], 16;" :: "r"(saddr), "l"(g));
}
__device__ __forceinline__ void ldsm4t(uint32_t* r, uint32_t addr) {
    asm volatile("ldmatrix.sync.aligned.m8n8.x4.trans.shared.b16 {%0,%1,%2,%3}, [%4];"
        : "=r"(r[0]), "=r"(r[1]), "=r"(r[2]), "=r"(r[3]) : "r"(addr));
}
__device__ __forceinline__ void mma_f16(float* c, const uint32_t* a, uint32_t b0, uint32_t b1) {
    asm volatile(
        "mma.sync.aligned.m16n8k16.row.col.f32.f16.f16.f32 "
        "{%0,%1,%2,%3}, {%4,%5,%6,%7}, {%8,%9}, {%0,%1,%2,%3};"
        : "+f"(c[0]), "+f"(c[1]), "+f"(c[2]), "+f"(c[3])
        : "r"(a[0]), "r"(a[1]), "r"(a[2]), "r"(a[3]), "r"(b0), "r"(b1));
}

// ---------------------------------------------------------------------------
// Kernel 1 (streaming prep, NO transpose): warp per token row.
// Zh[b][l][d] = half( sqrt(sqrt(eps+||x||^2)) * x[b][l][d] ).
// ---------------------------------------------------------------------------
__global__ __launch_bounds__(256)
void prep_kernel(const float* __restrict__ x) {
    int row  = blockIdx.x * 8 + threadIdx.y;      // 0 .. BATCH*LDIM-1
    int lane = threadIdx.x;
    const float4* p = (const float4*)(x + (size_t)row * DDIM);

    float4 v[6];
    float s = 0.f;
    #pragma unroll
    for (int i = 0; i < 6; i++) {
        v[i] = p[lane + i * 32];
        s = fmaf(v[i].x, v[i].x, s); s = fmaf(v[i].y, v[i].y, s);
        s = fmaf(v[i].z, v[i].z, s); s = fmaf(v[i].w, v[i].w, s);
    }
    #pragma unroll
    for (int o = 16; o > 0; o >>= 1) s += __shfl_xor_sync(0xffffffffu, s, o);
    s = __shfl_sync(0xffffffffu, s, 0);
    float sw = sqrtf(sqrtf(EPSF + s));            // sqrt(w)

    __half* z = g_Zh + (size_t)row * DDIM;
    #pragma unroll
    for (int i = 0; i < 6; i++) {
        __half2 h01 = __float22half2_rn(make_float2(v[i].x * sw, v[i].y * sw));
        __half2 h23 = __float22half2_rn(make_float2(v[i].z * sw, v[i].w * sw));
        *(uint2*)(z + (lane + i * 32) * 4) =
            make_uint2(*(uint32_t*)&h01, *(uint32_t*)&h23);
    }
}

// ---------------------------------------------------------------------------
// Kernel 2: 128x64 C tile from NATURAL-layout Zh via ldmatrix.trans.
// Smem: A = 64 k-rows x 256B (m-contig), B = 64 k-rows x 128B (n-contig),
// swizzle u ^= (krow & 7).  128 threads, warp tile 64x32 (2m x 2n warps).
// ---------------------------------------------------------------------------
extern __shared__ char smc[];

__global__ __launch_bounds__(128, 3)
void gram_tc_kernel(float* __restrict__ C) {
    int p = blockIdx.x % NTILES;
    int b = blockIdx.x / NTILES;
    int ti = 0, rem = p;
    while (rem >= 12 - 2 * ti) { rem -= 12 - 2 * ti; ti++; }
    int tj = 2 * ti + rem;                 // tj in [2*ti, 11]
    int m0 = ti * 128, n0 = tj * 64;

    const __half* __restrict__ Zb = g_Zh + (size_t)b * LDIM * DDIM;
    float* __restrict__ Cb = C + (size_t)b * DDIM * DDIM;

    int tid  = threadIdx.x;
    int wid  = tid >> 5, lane = tid & 31;
    int g = lane >> 2, t = lane & 3;
    int wm = (wid & 1) * 64;
    int wn = (wid >> 1) * 32;

    uint32_t sbase = (uint32_t)__cvta_generic_to_shared(smc);

    // cp.async A: 1024 chunks; base slot: rowA0 = tid>>4 (0..7), uA = tid&15;
    // i advances row by 8 -> swizzle (row&7) invariant.
    {
    }
    int rowA0 = tid >> 4, uA = tid & 15;
    uint32_t sA0 = rowA0 * 256 + ((uA ^ (rowA0 & 7)) << 4);          // + i*2048
    const __half* gA0 = Zb + (size_t)rowA0 * DDIM + m0 + uA * 8;     // + i*8*DDIM
    // cp.async B: 512 chunks; rowB0 = tid>>3 (0..15), uB = tid&7; i advances row by 16.
    int rowB0 = tid >> 3, uB = tid & 7;
    uint32_t sB0 = rowB0 * 128 + ((uB ^ (rowB0 & 7)) << 4);          // + i*2048
    const __half* gB0 = Zb + (size_t)rowB0 * DDIM + n0 + uB * 8;     // + i*16*DDIM

    auto ISSUE = [&](int chunk) {
        uint32_t base = sbase + (chunk % STAGES) * STAGE_BYTES;
        const __half* gk = (const __half*)0;
        size_t koff = (size_t)(chunk * BK) * DDIM;
        #pragma unroll
        for (int i = 0; i < 8; i++)
            cp16(base + sA0 + i * 2048, gA0 + koff + (size_t)i * 8 * DDIM);
        #pragma unroll
        for (int i = 0; i < 4; i++)
            cp16(base + A_BYTES + sB0 + i * 2048, gB0 + koff + (size_t)i * 16 * DDIM);
        (void)gk;
    };

    // ldmatrix.trans lane addressing (derived by duality from verified non-trans):
    // A: krow = (lane&7)+8*(lane>>4), m-off = 8*((lane>>3)&1)
    //    -> regs [m0k0, m8k0, m0k8, m8k8]
    // B: krow = (lane&7)+8*((lane>>3)&1), n-off = 8*(lane>>4)
    //    -> regs [n0k0, n0k8, n8k0, n8k8]
    int krowA = (lane & 7) + 8 * (lane >> 4);
    int moffu = (lane >> 3) & 1;                     // m-offset unit (0/1)
    uint32_t aoff[4];
    #pragma unroll
    for (int i = 0; i < 4; i++) {
        int mu = ((wm + 16 * i) >> 3) + moffu;       // 16B unit index (0..15)
        aoff[i] = krowA * 256 + ((mu ^ (krowA & 7)) << 4);
    }
    int krowB = (lane & 7) + 8 * ((lane >> 3) & 1);
    int noffu = lane >> 4;
    uint32_t boff[2];
    #pragma unroll
    for (int jp = 0; jp < 2; jp++) {
        int nu = ((wn + 16 * jp) >> 3) + noffu;      // 16B unit index (0..7)
        boff[jp] = krowB * 128 + ((nu ^ (krowB & 7)) << 4);
    }

    // Prologue
    #pragma unroll
    for (int c = 0; c < STAGES - 1; c++) {
        ISSUE(c);
        asm volatile("cp.async.commit_group;" ::: "memory");
    }

    float acc[4][4][4];
    #pragma unroll
    for (int i = 0; i < 4; i++)
        #pragma unroll
        for (int j = 0; j < 4; j++)
            #pragma unroll
            for (int r = 0; r < 4; r++) acc[i][j][r] = 0.f;

    for (int c = 0; c < NCHUNK; c++) {
        asm volatile("cp.async.wait_group %0;" :: "n"(STAGES - 2) : "memory");
        __syncthreads();

        if (c + STAGES - 1 < NCHUNK) ISSUE(c + STAGES - 1);
        asm volatile("cp.async.commit_group;" ::: "memory");

        uint32_t Ab = sbase + (c % STAGES) * STAGE_BYTES;
        uint32_t Bb = Ab + A_BYTES;

        #pragma unroll
        for (int ks = 0; ks < 4; ks++) {          // four k16 steps per BK=64
            uint32_t afr[4][4];
            #pragma unroll
            for (int i = 0; i < 4; i++)
                ldsm4t(afr[i], Ab + aoff[i] + ks * 4096);   // +16 k-rows * 256B
            uint32_t bfr[2][4];
            #pragma unroll
            for (int jp = 0; jp < 2; jp++)
                ldsm4t(bfr[jp], Bb + boff[jp] + ks * 2048); // +16 k-rows * 128B
            #pragma unroll
            for (int i = 0; i < 4; i++)
                #pragma unroll
                for (int j = 0; j < 4; j++)
                    mma_f16(acc[i][j], afr[i],
                            bfr[j >> 1][(j & 1) * 2], bfr[j >> 1][(j & 1) * 2 + 1]);
        }
    }

    // Epilogue: direct tile
    #pragma unroll
    for (int i = 0; i < 4; i++) {
        #pragma unroll
        for (int j = 0; j < 4; j++) {
            int m = m0 + wm + 16 * i + g;
            int n = n0 + wn + 8 * j + 2 * t;
            *(float2*)(Cb + (size_t)m * DDIM + n) =
                make_float2(acc[i][j][0], acc[i][j][1]);
            *(float2*)(Cb + (size_t)(m + 8) * DDIM + n) =
                make_float2(acc[i][j][2], acc[i][j][3]);
        }
    }
    // Mirror (always; overlapping writes carry identical values)
    #pragma unroll
    for (int i = 0; i < 4; i++) {
        #pragma unroll
        for (int j = 0; j < 4; j++) {
            int m = m0 + wm + 16 * i + g;
            int n = n0 + wn + 8 * j + 2 * t;
            Cb[(size_t)n * DDIM + m]           = acc[i][j][0];
            Cb[(size_t)(n + 1) * DDIM + m]     = acc[i][j][1];
            Cb[(size_t)n * DDIM + m + 8]       = acc[i][j][2];
            Cb[(size_t)(n + 1) * DDIM + m + 8] = acc[i][j][3];
        }
    }
}

// ---------------------------------------------------------------------------
extern "C" void kernel_launch(void* const* d_in, const int* in_sizes, int n_in,
                              void* d_out, int out_size) {
    const float* x = (const float*)d_in[0];
    float* out = (float*)d_out;

    static int configured = 0;
    if (!configured) {
        cudaFuncSetAttribute(gram_tc_kernel,
                             cudaFuncAttributeMaxDynamicSharedMemorySize, SMEM_BYTES);
        configured = 1;
    }

    prep_kernel<<<(BATCH * LDIM) / 8, dim3(32, 8)>>>(x);
    gram_tc_kernel<<<BATCH * NTILES, 128, SMEM_BYTES>>>(out);
}

// round 16
// speedup vs baseline: 1.4654x; 1.4654x over previous
#include <cuda_runtime.h>
#include <cuda_fp16.h>
#include <math.h>
#include <stdint.h>

// Problem shape
#define BATCH 32
#define LDIM  512
#define DDIM  768
#define EPSF  1e-5f

// Gram tiling: 128(m) x 64(n) tiles on the 6x12 (128-row x 64-col) grid.
// Cover: tj >= 2*ti  -> 42 tiles per batch (same FLOPs as 21 symmetric 128x128).
#define NTILES  42
#define BK      64                   // k (halfs) per stage = 128B rows
#define NCHUNK  (LDIM / BK)          // 8
#define STAGES  3
#define A_BYTES (128 * BK * 2)       // 16384
#define B_BYTES (64  * BK * 2)       // 8192
#define STAGE_BYTES (A_BYTES + B_BYTES)          // 24576
#define SMEM_BYTES  (STAGES * STAGE_BYTES)       // 73728

// Prep smem: 32 rows x 769 floats (odd pad -> conflict-free transpose) + 32 w's
#define PPAD 769
#define PREP_SMEM ((32 * PPAD + 32) * 4)         // 98560

// Scratch: transposed, weight-folded fp16 copy  Zh[b][d][l]  (24 MB)
__device__ __align__(16) __half g_Zh[BATCH * DDIM * LDIM];

__device__ __forceinline__ void cp16(uint32_t saddr, const void* g) {
    asm volatile("cp.async.cg.shared.global [%0], [%1], 16;" :: "r"(saddr), "l"(g));
}
__device__ __forceinline__ void ldsm4(uint32_t* r, uint32_t addr) {
    asm volatile("ldmatrix.sync.aligned.m8n8.x4.shared.b16 {%0,%1,%2,%3}, [%4];"
        : "=r"(r[0]), "=r"(r[1]), "=r"(r[2]), "=r"(r[3]) : "r"(addr));
}
__device__ __forceinline__ void mma_f16(float* c, const uint32_t* a, uint32_t b0, uint32_t b1) {
    asm volatile(
        "mma.sync.aligned.m16n8k16.row.col.f32.f16.f16.f32 "
        "{%0,%1,%2,%3}, {%4,%5,%6,%7}, {%8,%9}, {%0,%1,%2,%3};"
        : "+f"(c[0]), "+f"(c[1]), "+f"(c[2]), "+f"(c[3])
        : "r"(a[0]), "r"(a[1]), "r"(a[2]), "r"(a[3]), "r"(b0), "r"(b1));
}

// ---------------------------------------------------------------------------
// Kernel 1 (fused prep — verified R10 version): one pass over X.
// Warp owns 4 token rows: load -> smem + in-register sum of squares,
// then transposed fp16 store of sqrt(w)*x into Zh[b][d][l].
// ---------------------------------------------------------------------------
extern __shared__ float psh[];

__global__ __launch_bounds__(256, 2)
void prep_kernel(const float* __restrict__ x) {
    float* wbuf = psh + 32 * PPAD;
    int b  = blockIdx.y;
    int l0 = blockIdx.x * 32;
    const float* __restrict__ Xb = x + ((size_t)b * LDIM + l0) * DDIM;
    int tid = threadIdx.x;
    int wid = tid >> 5, lane = tid & 31;

    #pragma unroll
    for (int rr = 0; rr < 4; rr++) {
        int r = wid * 4 + rr;
        const float4* Xr = (const float4*)(Xb + (size_t)r * DDIM);
        float* dr = psh + r * PPAD;
        float s = 0.f;
        #pragma unroll
        for (int i = 0; i < 6; i++) {
            float4 v = Xr[lane + i * 32];
            float* d = dr + (lane + i * 32) * 4;
            d[0] = v.x; d[1] = v.y; d[2] = v.z; d[3] = v.w;
            s = fmaf(v.x, v.x, s); s = fmaf(v.y, v.y, s);
            s = fmaf(v.z, v.z, s); s = fmaf(v.w, v.w, s);
        }
        #pragma unroll
        for (int o = 16; o > 0; o >>= 1) s += __shfl_xor_sync(0xffffffffu, s, o);
        if (lane == 0) wbuf[r] = sqrtf(sqrtf(EPSF + s));   // sqrt(w)
    }
    __syncthreads();

    int li8 = (lane & 3) * 8;
    int dof = lane >> 2;
    float sw[8];
    #pragma unroll
    for (int q = 0; q < 8; q++) sw[q] = wbuf[li8 + q];
    __half* __restrict__ Zb = g_Zh + (size_t)b * DDIM * LDIM + l0;

    #pragma unroll 4
    for (int it = 0; it < 12; it++) {
        int dd = it * 64 + wid * 8 + dof;             // 0..767, disjoint cover
        __half2 h[4];
        #pragma unroll
        for (int q = 0; q < 4; q++) {
            float v0 = psh[(li8 + 2 * q)     * PPAD + dd] * sw[2 * q];
            float v1 = psh[(li8 + 2 * q + 1) * PPAD + dd] * sw[2 * q + 1];
            h[q] = __float22half2_rn(make_float2(v0, v1));
        }
        *(uint4*)(Zb + (size_t)dd * LDIM + li8) = *(uint4*)h;
    }
}

// ---------------------------------------------------------------------------
// Kernel 2 (verified R10 config + fully-unrolled mainloop): 128x64 C tile,
// 128 threads, 4 warps (2m x 2n), warp tile 64x32, BK=64, 3 stages,
// swizzle u^(row&7). Always mirror (duplicates carry identical values).
// ---------------------------------------------------------------------------
extern __shared__ char smc[];

__global__ __launch_bounds__(128, 3)
void gram_tc_kernel(float* __restrict__ C) {
    int p = blockIdx.x % NTILES;
    int b = blockIdx.x / NTILES;
    int ti = 0, rem = p;
    while (rem >= 12 - 2 * ti) { rem -= 12 - 2 * ti; ti++; }
    int tj = 2 * ti + rem;                 // tj in [2*ti, 11]
    int m0 = ti * 128, n0 = tj * 64;

    const __half* __restrict__ Zb = g_Zh + (size_t)b * DDIM * LDIM;
    float* __restrict__ Cb = C + (size_t)b * DDIM * DDIM;

    int tid  = threadIdx.x;
    int wid  = tid >> 5, lane = tid & 31;
    int g = lane >> 2, t = lane & 3;
    int wm = (wid & 1) * 64;
    int wn = (wid >> 1) * 32;

    uint32_t sbase = (uint32_t)__cvta_generic_to_shared(smc);

    const __half* gAr[8]; uint32_t sA[8];
    #pragma unroll
    for (int i = 0; i < 8; i++) {
        int j = tid + i * 128;
        int row = j >> 3, u = j & 7;
        gAr[i] = Zb + (size_t)(m0 + row) * LDIM + u * 8;
        sA[i]  = row * 128 + ((u ^ (row & 7)) << 4);
    }
    const __half* gBr[4]; uint32_t sB[4];
    #pragma unroll
    for (int i = 0; i < 4; i++) {
        int j = tid + i * 128;
        int row = j >> 3, u = j & 7;
        gBr[i] = Zb + (size_t)(n0 + row) * LDIM + u * 8;
        sB[i]  = row * 128 + ((u ^ (row & 7)) << 4);
    }

    auto ISSUE = [&](int chunk, uint32_t stage_base) {
        int kc = chunk * BK;
        #pragma unroll
        for (int i = 0; i < 8; i++) cp16(stage_base + sA[i], gAr[i] + kc);
        #pragma unroll
        for (int i = 0; i < 4; i++) cp16(stage_base + A_BYTES + sB[i], gBr[i] + kc);
    };

    int rowA[4], r7A[4];
    #pragma unroll
    for (int i = 0; i < 4; i++) {
        rowA[i] = wm + 16 * i + (lane & 7) + 8 * ((lane >> 3) & 1);
        r7A[i]  = rowA[i] & 7;
    }
    int uselA = lane >> 4;
    int rowB[2], r7B[2];
    #pragma unroll
    for (int jp = 0; jp < 2; jp++) {
        rowB[jp] = wn + 16 * jp + (lane & 7) + 8 * (lane >> 4);
        r7B[jp]  = rowB[jp] & 7;
    }
    int uselB = (lane >> 3) & 1;

    #pragma unroll
    for (int c = 0; c < STAGES - 1; c++) {
        ISSUE(c, sbase + c * STAGE_BYTES);
        asm volatile("cp.async.commit_group;" ::: "memory");
    }

    float acc[4][4][4];
    #pragma unroll
    for (int i = 0; i < 4; i++)
        #pragma unroll
        for (int j = 0; j < 4; j++)
            #pragma unroll
            for (int r = 0; r < 4; r++) acc[i][j][r] = 0.f;

    #pragma unroll
    for (int c = 0; c < NCHUNK; c++) {
        asm volatile("cp.async.wait_group %0;" :: "n"(STAGES - 2) : "memory");
        __syncthreads();

        if (c + STAGES - 1 < NCHUNK)
            ISSUE(c + STAGES - 1, sbase + ((c + STAGES - 1) % STAGES) * STAGE_BYTES);
        asm volatile("cp.async.commit_group;" ::: "memory");

        uint32_t Ab = sbase + (c % STAGES) * STAGE_BYTES;
        uint32_t Bb = Ab + A_BYTES;

        #pragma unroll
        for (int ks = 0; ks < 4; ks++) {          // four k16 steps per BK=64
            int ku = ks * 2;
            uint32_t afr[4][4];
            #pragma unroll
            for (int i = 0; i < 4; i++)
                ldsm4(afr[i], Ab + rowA[i] * 128
                               + (((ku + uselA) ^ r7A[i]) << 4));
            uint32_t bfr[2][4];
            #pragma unroll
            for (int jp = 0; jp < 2; jp++)
                ldsm4(bfr[jp], Bb + rowB[jp] * 128
                                + (((ku + uselB) ^ r7B[jp]) << 4));
            #pragma unroll
            for (int i = 0; i < 4; i++)
                #pragma unroll
                for (int j = 0; j < 4; j++)
                    mma_f16(acc[i][j], afr[i],
                            bfr[j >> 1][(j & 1) * 2], bfr[j >> 1][(j & 1) * 2 + 1]);
        }
    }

    // Epilogue: direct tile
    #pragma unroll
    for (int i = 0; i < 4; i++) {
        #pragma unroll
        for (int j = 0; j < 4; j++) {
            int m = m0 + wm + 16 * i + g;
            int n = n0 + wn + 8 * j + 2 * t;
            *(float2*)(Cb + (size_t)m * DDIM + n) =
                make_float2(acc[i][j][0], acc[i][j][1]);
            *(float2*)(Cb + (size_t)(m + 8) * DDIM + n) =
                make_float2(acc[i][j][2], acc[i][j][3]);
        }
    }
    // Mirror (always; overlapping writes carry identical values)
    #pragma unroll
    for (int i = 0; i < 4; i++) {
        #pragma unroll
        for (int j = 0; j < 4; j++) {
            int m = m0 + wm + 16 * i + g;
            int n = n0 + wn + 8 * j + 2 * t;
            Cb[(size_t)n * DDIM + m]           = acc[i][j][0];
            Cb[(size_t)(n + 1) * DDIM + m]     = acc[i][j][1];
            Cb[(size_t)n * DDIM + m + 8]       = acc[i][j][2];
            Cb[(size_t)(n + 1) * DDIM + m + 8] = acc[i][j][3];
        }
    }
}

// ---------------------------------------------------------------------------
extern "C" void kernel_launch(void* const* d_in, const int* in_sizes, int n_in,
                              void* d_out, int out_size) {
    const float* x = (const float*)d_in[0];
    float* out = (float*)d_out;

    static int configured = 0;
    if (!configured) {
        cudaFuncSetAttribute(gram_tc_kernel,
                             cudaFuncAttributeMaxDynamicSharedMemorySize, SMEM_BYTES);
        cudaFuncSetAttribute(prep_kernel,
                             cudaFuncAttributeMaxDynamicSharedMemorySize, PREP_SMEM);
        configured = 1;
    }

    prep_kernel<<<dim3(LDIM / 32, BATCH), 256, PREP_SMEM>>>(x);
    gram_tc_kernel<<<BATCH * NTILES, 128, SMEM_BYTES>>>(out);
}